// round 3
// baseline (speedup 1.0000x reference)
#include <cuda_runtime.h>
#include <cstdint>
#include <cstddef>

#define DINL __device__ __forceinline__

static constexpr int S_STAGES = 4;       // cp.async pipeline depth
static constexpr int KCHUNK   = 32;      // fp32 K elems per chunk (128 B rows)
static constexpr int MT       = 128;     // CTA M tile
static constexpr int NT       = 128;     // CTA N tile (= D_OUT)
static constexpr int ROW_F    = 40;      // smem row stride in floats (160 B): bank-conflict-free
static constexpr int TILE_F   = 128 * ROW_F;          // 5120 floats = 20480 B
static constexpr int STAGE_F  = 2 * TILE_F;           // A + B
static constexpr int SMEM_TOTAL = S_STAGES * STAGE_F * 4;  // 163840 B

static constexpr int M_TOTAL = 16384;
static constexpr int D_IN    = 512;
static constexpr int D_OUT   = 128;

// Scratch (static device globals: allocation-free).
__device__ float g_xT[(size_t)D_OUT * M_TOTAL];  // x^T  [128][16384]  (K-major B for GEMM2)
__device__ float g_WT[(size_t)D_OUT * D_IN];     // W^T  [128][512]    (K-major B for GEMM1)

// ---------------------------------------------------------------- helpers
DINL uint32_t smem_u32(const void* p) {
    uint32_t a;
    asm("{ .reg .u64 t; cvta.to.shared.u64 t, %1; cvt.u32.u64 %0, t; }"
        : "=r"(a) : "l"(p));
    return a;
}
DINL void cp16(uint32_t saddr, const float* g) {
    asm volatile("cp.async.cg.shared.global [%0], [%1], 16;"
                 :: "r"(saddr), "l"(g));
}
DINL uint32_t f2tf(float f) {   // round-to-nearest tf32 (unbiased)
    uint32_t r;
    asm("cvt.rna.tf32.f32 %0, %1;" : "=r"(r) : "f"(f));
    return r;
}
DINL void mma_tf32(float* c, const uint32_t* a, const uint32_t* b) {
    asm volatile(
        "mma.sync.aligned.m16n8k8.row.col.f32.tf32.tf32.f32 "
        "{%0,%1,%2,%3}, {%4,%5,%6,%7}, {%8,%9}, {%0,%1,%2,%3};"
        : "+f"(c[0]), "+f"(c[1]), "+f"(c[2]), "+f"(c[3])
        : "r"(a[0]), "r"(a[1]), "r"(a[2]), "r"(a[3]), "r"(b[0]), "r"(b[1]));
}

// ---------------------------------------------------------------- kernels
__global__ void transposeW_kernel(const float* __restrict__ W, float* __restrict__ WT) {
    int t = blockIdx.x * blockDim.x + threadIdx.x;   // 65536 threads
    int k = t >> 7, n = t & 127;                     // W[512][128]
    WT[(size_t)n * D_IN + k] = W[(size_t)k * D_OUT + n];
}

// C[M,NT] = A[M,K] @ B'[NT,K]^T  (A row-major ld=K; B' = B^T row-major ld=K)
// TRANS_EPI: write result transposed into C[NT][M_TOTAL].
template <bool TRANS_EPI>
__global__ void __launch_bounds__(256, 1)
gemm_tc(const float* __restrict__ A, const float* __restrict__ B,
        float* __restrict__ C, int K)
{
    extern __shared__ __align__(16) float smem[];
    const uint32_t sbase = smem_u32(smem);
    const int tid  = threadIdx.x;
    const int wid  = tid >> 5, lane = tid & 31;
    const int m0   = blockIdx.x * MT;
    const int NC   = K / KCHUNK;
    const int mw   = (wid >> 2) * 64;      // warp M offset in tile (2 rows of warps)
    const int nw   = (wid & 3)  * 32;      // warp N offset (4 cols of warps)
    const int rg   = lane >> 2;            // row group 0..7
    const int c2   = (lane & 3) * 2;       // k-slot base (remapped contiguous)

    auto load_chunk = [&](int chunk, int stage) {
        const float* ga = A + (size_t)m0 * K + (size_t)chunk * KCHUNK;
        const float* gb = B + (size_t)chunk * KCHUNK;
        uint32_t sa  = sbase + (uint32_t)(stage * STAGE_F) * 4u;
        uint32_t sbb = sa + (uint32_t)TILE_F * 4u;
#pragma unroll
        for (int t = 0; t < 4; ++t) {                // 1024 16B chunks / 256 thr
            int idx = tid + 256 * t;
            int row = idx >> 3, c = idx & 7;         // 8 x 16B per 128B data row
            uint32_t so = (uint32_t)(row * ROW_F + c * 4) * 4u;
            cp16(sa  + so, ga + (size_t)row * K + c * 4);
            cp16(sbb + so, gb + (size_t)row * K + c * 4);
        }
    };

    float acc[4][4][4];                       // [m-tile][n-tile][frag]
#pragma unroll
    for (int i = 0; i < 4; ++i)
#pragma unroll
        for (int j = 0; j < 4; ++j)
#pragma unroll
            for (int f = 0; f < 4; ++f) acc[i][j][f] = 0.f;

    // Prologue: fill S-1 stages
#pragma unroll
    for (int s = 0; s < S_STAGES - 1; ++s) {
        if (s < NC) load_chunk(s, s);
        asm volatile("cp.async.commit_group;" ::: "memory");
    }

    for (int kc = 0; kc < NC; ++kc) {
        asm volatile("cp.async.wait_group %0;" :: "n"(S_STAGES - 2) : "memory");
        __syncthreads();

        // issue next loads first (overlap with compute below)
        {
            int nxt = kc + S_STAGES - 1;
            if (nxt < NC) load_chunk(nxt, nxt & (S_STAGES - 1));
            asm volatile("cp.async.commit_group;" ::: "memory");
        }

        const float* As = smem + (kc & (S_STAGES - 1)) * STAGE_F;
        const float* Bs = As + TILE_F;
#pragma unroll
        for (int kk = 0; kk < 4; ++kk) {      // 4 x k8 steps
            const int kb = kk * 8 + c2;
            uint32_t a[4][4];
#pragma unroll
            for (int i = 0; i < 4; ++i) {
                const float2 u = *(const float2*)(As + (mw + i * 16 + rg) * ROW_F + kb);
                const float2 v = *(const float2*)(As + (mw + i * 16 + rg + 8) * ROW_F + kb);
                a[i][0] = f2tf(u.x); a[i][1] = f2tf(v.x);
                a[i][2] = f2tf(u.y); a[i][3] = f2tf(v.y);
            }
            uint32_t b[4][2];
#pragma unroll
            for (int j = 0; j < 4; ++j) {
                const float2 w = *(const float2*)(Bs + (nw + j * 8 + rg) * ROW_F + kb);
                b[j][0] = f2tf(w.x); b[j][1] = f2tf(w.y);
            }
#pragma unroll
            for (int i = 0; i < 4; ++i)
#pragma unroll
                for (int j = 0; j < 4; ++j)
                    mma_tf32(acc[i][j], a[i], b[j]);
        }
    }

    // Epilogue
#pragma unroll
    for (int i = 0; i < 4; ++i) {
        const int row0 = m0 + mw + i * 16 + rg;
#pragma unroll
        for (int j = 0; j < 4; ++j) {
            const int col0 = nw + j * 8 + c2;
            if (TRANS_EPI) {
                C[(size_t)col0       * M_TOTAL + row0]     = acc[i][j][0];
                C[(size_t)(col0 + 1) * M_TOTAL + row0]     = acc[i][j][1];
                C[(size_t)col0       * M_TOTAL + row0 + 8] = acc[i][j][2];
                C[(size_t)(col0 + 1) * M_TOTAL + row0 + 8] = acc[i][j][3];
            } else {
                *(float2*)(C + (size_t)row0 * NT + col0) =
                    make_float2(acc[i][j][0], acc[i][j][1]);
                *(float2*)(C + (size_t)(row0 + 8) * NT + col0) =
                    make_float2(acc[i][j][2], acc[i][j][3]);
            }
        }
    }
}

// ---------------------------------------------------------------- launch
extern "C" void kernel_launch(void* const* d_in, const int* in_sizes, int n_in,
                              void* d_out, int out_size)
{
    const float* inputs = nullptr;
    const float* adj = nullptr;
    const float* weights = nullptr;
    for (int i = 0; i < n_in; ++i) {
        long sz = (long)in_sizes[i];
        if (sz == (long)M_TOTAL * D_IN)         inputs  = (const float*)d_in[i];
        else if (sz == (long)M_TOTAL * M_TOTAL) adj     = (const float*)d_in[i];
        else if (sz == (long)D_IN * D_OUT)      weights = (const float*)d_in[i];
    }

    float* xT = nullptr;
    float* WT = nullptr;
    cudaGetSymbolAddress((void**)&xT, g_xT);
    cudaGetSymbolAddress((void**)&WT, g_WT);
    cudaFuncSetAttribute((const void*)gemm_tc<true>,
                         cudaFuncAttributeMaxDynamicSharedMemorySize, SMEM_TOTAL);
    cudaFuncSetAttribute((const void*)gemm_tc<false>,
                         cudaFuncAttributeMaxDynamicSharedMemorySize, SMEM_TOTAL);

    // 1) WT = W^T (K-major B operand for GEMM1)
    transposeW_kernel<<<(D_IN * D_OUT) / 256, 256>>>(weights, WT);
    // 2) xT = (inputs @ W)^T  (transposed epilogue -> K-major B for GEMM2)
    gemm_tc<true><<<M_TOTAL / MT, 256, SMEM_TOTAL>>>(inputs, WT, xT, D_IN);
    // 3) out = adj @ x
    gemm_tc<false><<<M_TOTAL / MT, 256, SMEM_TOTAL>>>(adj, xT, (float*)d_out, M_TOTAL);
}

// round 4
// speedup vs baseline: 1.1437x; 1.1437x over previous
#include <cuda_runtime.h>
#include <cstdint>
#include <cstddef>

#define DINL __device__ __forceinline__

static constexpr int KCHUNK  = 32;                 // K per pipeline chunk
static constexpr int ROW_F   = 36;                 // smem row stride (144 B): conflict-free
static constexpr int TILE_F  = 128 * ROW_F;        // 4608 floats / tile
static constexpr int STAGE_F = 2 * TILE_F;         // A + B
static constexpr int S_STAGES = 2;
static constexpr int SMEM_BYTES = S_STAGES * STAGE_F * 4;   // 73728 B -> 2 CTAs/SM

static constexpr int M_TOTAL = 16384;
static constexpr int D_IN    = 512;
static constexpr int D_OUT   = 128;
static constexpr int KSPLIT  = 8;
static constexpr int CH_UNIT = (M_TOTAL / KCHUNK) / KSPLIT;   // 64 chunks / unit
static constexpr int UNITS   = (M_TOTAL / 128) * KSPLIT;      // 1024 work units

// Static scratch (allocation-free).
__device__ float g_xT[(size_t)D_OUT * M_TOTAL];               // x^T, tf32-prerounded
__device__ float g_WT[(size_t)D_OUT * D_IN];                  // W^T, tf32-prerounded
__device__ float g_part[(size_t)KSPLIT * M_TOTAL * D_OUT];    // split-K partials (64 MB)
__device__ unsigned g_ticket;

// ---------------------------------------------------------------- helpers
DINL uint32_t smem_u32(const void* p) {
    uint32_t a;
    asm("{ .reg .u64 t; cvta.to.shared.u64 t, %1; cvt.u32.u64 %0, t; }"
        : "=r"(a) : "l"(p));
    return a;
}
DINL void cp16(uint32_t saddr, const float* g) {
    asm volatile("cp.async.cg.shared.global [%0], [%1], 16;"
                 :: "r"(saddr), "l"(g));
}
DINL uint32_t f2tf(float f) {   // round-to-nearest tf32 (unbiased)
    uint32_t r;
    asm("cvt.rna.tf32.f32 %0, %1;" : "=r"(r) : "f"(f));
    return r;
}
DINL void mma_tf32(float* c, const uint32_t* a, const uint32_t* b) {
    asm volatile(
        "mma.sync.aligned.m16n8k8.row.col.f32.tf32.tf32.f32 "
        "{%0,%1,%2,%3}, {%4,%5,%6,%7}, {%8,%9}, {%0,%1,%2,%3};"
        : "+f"(c[0]), "+f"(c[1]), "+f"(c[2]), "+f"(c[3])
        : "r"(a[0]), "r"(a[1]), "r"(a[2]), "r"(a[3]), "r"(b[0]), "r"(b[1]));
}

// ---------------------------------------------------------------- kernels
// W[512][128] -> WT[128][512] with tf32 pre-round; also resets the ticket.
__global__ void transposeW_kernel(const float* __restrict__ W, float* __restrict__ WT) {
    if (blockIdx.x == 0 && threadIdx.x == 0) g_ticket = 0u;
    int t = blockIdx.x * blockDim.x + threadIdx.x;   // 65536 threads
    int k = t >> 7, n = t & 127;
    WT[(size_t)n * D_IN + k] = __uint_as_float(f2tf(W[(size_t)k * D_OUT + n]));
}

// C tile = A[128 rows, K] @ B[128 rows, K]^T.  B is tf32-prerounded (no cvt).
// QUEUE: persistent, ticket-scheduled (mt, ksplit) units -> g_part.
// TRANS_EPI: write result transposed [col][M_TOTAL] with tf32 pre-round.
template <bool TRANS_EPI, bool QUEUE>
__global__ void __launch_bounds__(256, 2)
gemm_tc(const float* __restrict__ A, const float* __restrict__ B,
        float* __restrict__ C, int K, int nchunks)
{
    extern __shared__ __align__(16) float smem[];
    __shared__ unsigned s_unit;
    const uint32_t sbase = smem_u32(smem);
    const int tid  = threadIdx.x;
    const int wid  = tid >> 5, lane = tid & 31;
    const int mw   = (wid >> 2) * 64;     // 2 m-groups x 4 n-groups of warps
    const int nw   = (wid & 3)  * 32;
    const int rg   = lane >> 2;           // row group 0..7
    const int c2   = (lane & 3) * 2;      // contiguous k-slot remap

    for (;;) {
        int mt, ks;
        if (QUEUE) {
            if (tid == 0) s_unit = atomicAdd(&g_ticket, 1u);
            __syncthreads();
            unsigned u = s_unit;
            if (u >= (unsigned)UNITS) return;
            mt = (int)(u & 127u); ks = (int)(u >> 7);
        } else {
            mt = blockIdx.x; ks = 0;
        }

        const float* a0 = A + (size_t)mt * 128 * K + (size_t)ks * CH_UNIT * KCHUNK;
        const float* b0 = B + (size_t)ks * CH_UNIT * KCHUNK;

        auto load_chunk = [&](int chunk, int stage) {
            const float* ga = a0 + (size_t)chunk * KCHUNK;
            const float* gb = b0 + (size_t)chunk * KCHUNK;
            uint32_t sa  = sbase + (uint32_t)(stage * STAGE_F) * 4u;
            uint32_t sbb = sa + (uint32_t)TILE_F * 4u;
#pragma unroll
            for (int t4 = 0; t4 < 4; ++t4) {          // 1024 x 16B per tile pair
                int idx = tid + 256 * t4;
                int row = idx >> 3, c = idx & 7;
                uint32_t so = (uint32_t)(row * ROW_F + c * 4) * 4u;
                cp16(sa  + so, ga + (size_t)row * K + c * 4);
                cp16(sbb + so, gb + (size_t)row * K + c * 4);
            }
        };

        float acc[4][4][4];
#pragma unroll
        for (int i = 0; i < 4; ++i)
#pragma unroll
            for (int j = 0; j < 4; ++j)
#pragma unroll
                for (int f = 0; f < 4; ++f) acc[i][j][f] = 0.f;

        // Prologue: fill both stages
        load_chunk(0, 0);
        asm volatile("cp.async.commit_group;" ::: "memory");
        if (nchunks > 1) load_chunk(1, 1);
        asm volatile("cp.async.commit_group;" ::: "memory");

        for (int kc = 0; kc < nchunks; ++kc) {
            asm volatile("cp.async.wait_group 1;" ::: "memory");
            __syncthreads();

            const float* As = smem + (kc & 1) * STAGE_F;
            const float* Bs = As + TILE_F;
#pragma unroll
            for (int kk = 0; kk < 4; ++kk) {
                const int kb = kk * 8 + c2;
                uint32_t a[4][4];
#pragma unroll
                for (int i = 0; i < 4; ++i) {
                    const float2 u = *(const float2*)(As + (mw + i * 16 + rg) * ROW_F + kb);
                    const float2 v = *(const float2*)(As + (mw + i * 16 + rg + 8) * ROW_F + kb);
                    a[i][0] = f2tf(u.x); a[i][1] = f2tf(v.x);
                    a[i][2] = f2tf(u.y); a[i][3] = f2tf(v.y);
                }
                uint32_t b[4][2];
#pragma unroll
                for (int j = 0; j < 4; ++j) {   // B pre-rounded: raw bits
                    const float2 w = *(const float2*)(Bs + (nw + j * 8 + rg) * ROW_F + kb);
                    b[j][0] = __float_as_uint(w.x); b[j][1] = __float_as_uint(w.y);
                }
#pragma unroll
                for (int i = 0; i < 4; ++i)
#pragma unroll
                    for (int j = 0; j < 4; ++j)
                        mma_tf32(acc[i][j], a[i], b[j]);
            }
            __syncthreads();                     // all reads of stage (kc&1) done
            if (kc + 2 < nchunks) load_chunk(kc + 2, kc & 1);
            asm volatile("cp.async.commit_group;" ::: "memory");
        }

        // Epilogue
        float* cb = QUEUE ? C + (size_t)ks * M_TOTAL * D_OUT + (size_t)mt * 128 * D_OUT
                          : C;
#pragma unroll
        for (int i = 0; i < 4; ++i) {
            const int rloc = mw + i * 16 + rg;
#pragma unroll
            for (int j = 0; j < 4; ++j) {
                const int col = nw + j * 8 + c2;
                if (TRANS_EPI) {                 // pre-round to tf32 for GEMM2 B
                    const int grow = mt * 128 + rloc;
                    C[(size_t)col       * M_TOTAL + grow]     = __uint_as_float(f2tf(acc[i][j][0]));
                    C[(size_t)(col + 1) * M_TOTAL + grow]     = __uint_as_float(f2tf(acc[i][j][1]));
                    C[(size_t)col       * M_TOTAL + grow + 8] = __uint_as_float(f2tf(acc[i][j][2]));
                    C[(size_t)(col + 1) * M_TOTAL + grow + 8] = __uint_as_float(f2tf(acc[i][j][3]));
                } else {
                    *(float2*)(cb + (size_t)rloc * D_OUT + col) =
                        make_float2(acc[i][j][0], acc[i][j][1]);
                    *(float2*)(cb + (size_t)(rloc + 8) * D_OUT + col) =
                        make_float2(acc[i][j][2], acc[i][j][3]);
                }
            }
        }
        if (!QUEUE) return;
    }
}

// out = sum over KSPLIT partials (vectorized float4)
__global__ void reduce_kernel(float* __restrict__ out) {
    const size_t i = (size_t)blockIdx.x * blockDim.x + threadIdx.x;  // 524288 f4
    const float4* p = reinterpret_cast<const float4*>(g_part);
    const size_t stride = (size_t)M_TOTAL * D_OUT / 4;
    float4 s = p[i];
#pragma unroll
    for (int k = 1; k < KSPLIT; ++k) {
        float4 t = p[i + (size_t)k * stride];
        s.x += t.x; s.y += t.y; s.z += t.z; s.w += t.w;
    }
    reinterpret_cast<float4*>(out)[i] = s;
}

// ---------------------------------------------------------------- launch
extern "C" void kernel_launch(void* const* d_in, const int* in_sizes, int n_in,
                              void* d_out, int out_size)
{
    const float* inputs = nullptr;
    const float* adj = nullptr;
    const float* weights = nullptr;
    for (int i = 0; i < n_in; ++i) {
        long sz = (long)in_sizes[i];
        if (sz == (long)M_TOTAL * D_IN)         inputs  = (const float*)d_in[i];
        else if (sz == (long)M_TOTAL * M_TOTAL) adj     = (const float*)d_in[i];
        else if (sz == (long)D_IN * D_OUT)      weights = (const float*)d_in[i];
    }

    float *xT = nullptr, *WT = nullptr, *part = nullptr;
    cudaGetSymbolAddress((void**)&xT, g_xT);
    cudaGetSymbolAddress((void**)&WT, g_WT);
    cudaGetSymbolAddress((void**)&part, g_part);
    cudaFuncSetAttribute((const void*)gemm_tc<true,  false>,
                         cudaFuncAttributeMaxDynamicSharedMemorySize, SMEM_BYTES);
    cudaFuncSetAttribute((const void*)gemm_tc<false, true>,
                         cudaFuncAttributeMaxDynamicSharedMemorySize, SMEM_BYTES);

    // 1) WT = tf32(W^T); reset ticket
    transposeW_kernel<<<(D_IN * D_OUT) / 256, 256>>>(weights, WT);
    // 2) xT = tf32((inputs @ W)^T)
    gemm_tc<true,  false><<<M_TOTAL / 128, 256, SMEM_BYTES>>>(inputs, WT, xT, D_IN, D_IN / KCHUNK);
    // 3) partials = adj @ x  (persistent, ticket-scheduled, split-K=8)
    gemm_tc<false, true><<<296, 256, SMEM_BYTES>>>(adj, xT, part, M_TOTAL, CH_UNIT);
    // 4) out = sum partials
    reduce_kernel<<<(M_TOTAL * D_OUT / 4) / 256, 256>>>((float*)d_out);
}

// round 5
// speedup vs baseline: 1.5889x; 1.3893x over previous
#include <cuda_runtime.h>
#include <cuda_fp16.h>
#include <cstdint>
#include <cstddef>

#define DINL __device__ __forceinline__

static constexpr int KCHUNK   = 32;              // K elems per chunk
static constexpr int ROW_B    = 80;              // smem row stride bytes (64B data + 16 pad)
static constexpr int TILE_B   = 128 * ROW_B;     // 10240 B per fp16 tile
static constexpr int A_STAGES = 2;
static constexpr int B_STAGES = 4;
static constexpr int SMEM_BYTES = (A_STAGES + B_STAGES) * TILE_B;   // 61440

static constexpr int M_TOTAL = 16384;
static constexpr int D_IN    = 512;
static constexpr int D_OUT   = 128;
static constexpr int KSPLIT  = 8;
static constexpr int CH_UNIT = (M_TOTAL / KCHUNK) / KSPLIT;   // 64 chunks / unit
static constexpr int UNITS   = (M_TOTAL / 128) * KSPLIT;      // 1024 units

// Static scratch (allocation-free).
__device__ __half g_xT[(size_t)D_OUT * M_TOTAL];              // x^T fp16 [128][16384]
__device__ __half g_WT[(size_t)D_OUT * D_IN];                 // W^T fp16 [128][512]
__device__ float  g_part[(size_t)KSPLIT * M_TOTAL * D_OUT];   // split-K partials
__device__ unsigned g_ticket;

// ---------------------------------------------------------------- helpers
DINL uint32_t smem_u32(const void* p) {
    uint32_t a;
    asm("{ .reg .u64 t; cvta.to.shared.u64 t, %1; cvt.u32.u64 %0, t; }"
        : "=r"(a) : "l"(p));
    return a;
}
DINL void cp16(uint32_t saddr, const void* g) {
    asm volatile("cp.async.cg.shared.global [%0], [%1], 16;"
                 :: "r"(saddr), "l"(g));
}
DINL uint32_t pack_h2(float lo, float hi) {    // -> {lo in [15:0], hi in [31:16]}
    uint32_t r;
    asm("cvt.rn.f16x2.f32 %0, %1, %2;" : "=r"(r) : "f"(hi), "f"(lo));
    return r;
}
DINL void sts64(uint32_t a, uint32_t w0, uint32_t w1) {
    asm volatile("st.shared.v2.b32 [%0], {%1, %2};" :: "r"(a), "r"(w0), "r"(w1) : "memory");
}
DINL void ldsm4(uint32_t* r, uint32_t addr) {
    asm volatile("ldmatrix.sync.aligned.m8n8.x4.shared.b16 {%0,%1,%2,%3}, [%4];"
                 : "=r"(r[0]), "=r"(r[1]), "=r"(r[2]), "=r"(r[3]) : "r"(addr));
}
DINL void mma_f16(float* c, const uint32_t* a, const uint32_t* b) {
    asm volatile(
        "mma.sync.aligned.m16n8k16.row.col.f32.f16.f16.f32 "
        "{%0,%1,%2,%3}, {%4,%5,%6,%7}, {%8,%9}, {%0,%1,%2,%3};"
        : "+f"(c[0]), "+f"(c[1]), "+f"(c[2]), "+f"(c[3])
        : "r"(a[0]), "r"(a[1]), "r"(a[2]), "r"(a[3]), "r"(b[0]), "r"(b[1]));
}

// ---------------------------------------------------------------- kernels
// W[512][128] -> WT fp16 [128][512]; resets the ticket.
__global__ void transposeW_kernel(const float* __restrict__ W, __half* __restrict__ WT) {
    if (blockIdx.x == 0 && threadIdx.x == 0) g_ticket = 0u;
    int t = blockIdx.x * blockDim.x + threadIdx.x;   // 65536 threads
    int k = t >> 7, n = t & 127;
    WT[(size_t)n * D_IN + k] = __float2half_rn(W[(size_t)k * D_OUT + n]);
}

// C-tile = A[128, K](fp32) @ B[128, K](fp16)^T, fp16 MMA, fp32 accum.
// QUEUE: persistent ticket (mt, ks) units -> g_part.   TRANS_EPI: C^T as fp16.
template <bool TRANS_EPI, bool QUEUE>
__global__ void __launch_bounds__(256, 2)
gemm_f16(const float* __restrict__ A, const __half* __restrict__ B,
         float* __restrict__ C, int K, int nchunks)
{
    extern __shared__ __align__(16) char smem[];
    __shared__ unsigned s_unit;
    const uint32_t sA = smem_u32(smem);                  // 2 fp16 A stages
    const uint32_t sB = sA + A_STAGES * TILE_B;          // 4 fp16 B stages
    const int tid  = threadIdx.x;
    const int wid  = tid >> 5, lane = tid & 31;
    const int mw   = (wid >> 2) * 64;                    // warp 64x32 tiles, 2x4 grid
    const int nw   = (wid & 3)  * 32;
    const int rg   = lane >> 2;                          // mma row group
    const int cc   = (lane & 3) * 2;                     // mma col pair base
    // ldmatrix per-lane address components
    const int a_r  = (lane & 7) + ((lane >> 3) & 1) * 8; // A: groups 1,3 -> +8 rows
    const int a_k  = (lane >> 4) * 16;                   // A: groups 2,3 -> +16B k
    const int b_r  = (lane & 7) + ((lane >> 4) & 1) * 8; // B: groups 2,3 -> +8 rows
    const int b_k  = ((lane >> 3) & 1) * 16;             // B: groups 1,3 -> +16B k
    // A LDG/STS per-thread granules (4 x 16B fp32 -> 4 x 8B fp16)
    int arow[4], acol[4];
#pragma unroll
    for (int g = 0; g < 4; ++g) { int idx = tid + 256 * g; arow[g] = idx >> 3; acol[g] = idx & 7; }
    // B cp.async granules (2 x 16B fp16)
    int brow[2], bcol[2];
#pragma unroll
    for (int g = 0; g < 2; ++g) { int idx = tid + 256 * g; brow[g] = idx >> 2; bcol[g] = idx & 3; }

    for (;;) {
        int mt, ks;
        if (QUEUE) {
            if (tid == 0) s_unit = atomicAdd(&g_ticket, 1u);
            __syncthreads();
            unsigned u = s_unit;
            if (u >= (unsigned)UNITS) return;
            mt = (int)(u & 127u); ks = (int)(u >> 7);
        } else {
            mt = blockIdx.x; ks = 0;
            __syncthreads();   // harmless; keeps paths symmetric
        }

        const float*  a0 = A + (size_t)mt * 128 * K + (size_t)ks * CH_UNIT * KCHUNK;
        const __half* b0 = B + (size_t)ks * CH_UNIT * KCHUNK;

        auto ldg_A = [&](int chunk, float4* st) {
            const float* ga = a0 + (size_t)chunk * KCHUNK;
#pragma unroll
            for (int g = 0; g < 4; ++g)
                st[g] = *(const float4*)(ga + (size_t)arow[g] * K + acol[g] * 4);
        };
        auto cp_B = [&](int chunk) {
            const __half* gb = b0 + (size_t)chunk * KCHUNK;
            uint32_t dst = sB + (chunk & (B_STAGES - 1)) * TILE_B;
#pragma unroll
            for (int g = 0; g < 2; ++g)
                cp16(dst + brow[g] * ROW_B + bcol[g] * 16,
                     gb + (size_t)brow[g] * K + bcol[g] * 8);
        };

        float acc[4][4][4];
#pragma unroll
        for (int i = 0; i < 4; ++i)
#pragma unroll
            for (int j = 0; j < 4; ++j)
#pragma unroll
                for (int f = 0; f < 4; ++f) acc[i][j][f] = 0.f;

        float4 st[4];
        ldg_A(0, st);
        cp_B(0); asm volatile("cp.async.commit_group;" ::: "memory");
        cp_B(1); asm volatile("cp.async.commit_group;" ::: "memory");
        cp_B(2); asm volatile("cp.async.commit_group;" ::: "memory");

        for (int kc = 0; kc < nchunks; ++kc) {
            asm volatile("cp.async.wait_group 2;" ::: "memory");   // B(kc) ready
            // convert + store A(kc) (regs loaded previous iter)
            {
                uint32_t abuf = sA + (kc & 1) * TILE_B;
#pragma unroll
                for (int g = 0; g < 4; ++g) {
                    uint32_t w0 = pack_h2(st[g].x, st[g].y);
                    uint32_t w1 = pack_h2(st[g].z, st[g].w);
                    sts64(abuf + arow[g] * ROW_B + acol[g] * 8, w0, w1);
                }
            }
            __syncthreads();
            if (kc + 3 < nchunks) cp_B(kc + 3);
            asm volatile("cp.async.commit_group;" ::: "memory");
            if (kc + 1 < nchunks) ldg_A(kc + 1, st);

            const uint32_t abuf = sA + (kc & 1) * TILE_B;
            const uint32_t bbuf = sB + (kc & (B_STAGES - 1)) * TILE_B;
#pragma unroll
            for (int kk = 0; kk < 2; ++kk) {
                uint32_t a[4][4];
#pragma unroll
                for (int i = 0; i < 4; ++i)
                    ldsm4(a[i], abuf + (mw + i * 16 + a_r) * ROW_B + a_k + kk * 32);
                uint32_t b[2][4];
#pragma unroll
                for (int jp = 0; jp < 2; ++jp)
                    ldsm4(b[jp], bbuf + (nw + jp * 16 + b_r) * ROW_B + b_k + kk * 32);
#pragma unroll
                for (int i = 0; i < 4; ++i)
#pragma unroll
                    for (int j = 0; j < 4; ++j)
                        mma_f16(acc[i][j], a[i], &b[j >> 1][(j & 1) * 2]);
            }
        }

        // Epilogue
#pragma unroll
        for (int i = 0; i < 4; ++i) {
            const int rloc = mw + i * 16 + rg;
#pragma unroll
            for (int j = 0; j < 4; ++j) {
                const int col = nw + j * 8 + cc;
                if (TRANS_EPI) {           // write x^T as fp16
                    __half* X = reinterpret_cast<__half*>(C);
                    const int grow = mt * 128 + rloc;
                    X[(size_t)col       * M_TOTAL + grow]     = __float2half_rn(acc[i][j][0]);
                    X[(size_t)(col + 1) * M_TOTAL + grow]     = __float2half_rn(acc[i][j][1]);
                    X[(size_t)col       * M_TOTAL + grow + 8] = __float2half_rn(acc[i][j][2]);
                    X[(size_t)(col + 1) * M_TOTAL + grow + 8] = __float2half_rn(acc[i][j][3]);
                } else {
                    float* cb = C + (size_t)ks * M_TOTAL * D_OUT + (size_t)mt * 128 * D_OUT;
                    *(float2*)(cb + (size_t)rloc * D_OUT + col) =
                        make_float2(acc[i][j][0], acc[i][j][1]);
                    *(float2*)(cb + (size_t)(rloc + 8) * D_OUT + col) =
                        make_float2(acc[i][j][2], acc[i][j][3]);
                }
            }
        }
        if (!QUEUE) return;
    }
}

// out = sum over KSPLIT partials
__global__ void reduce_kernel(float* __restrict__ out) {
    const size_t i = (size_t)blockIdx.x * blockDim.x + threadIdx.x;  // 524288 f4
    const float4* p = reinterpret_cast<const float4*>(g_part);
    const size_t stride = (size_t)M_TOTAL * D_OUT / 4;
    float4 s = p[i];
#pragma unroll
    for (int k = 1; k < KSPLIT; ++k) {
        float4 t = p[i + (size_t)k * stride];
        s.x += t.x; s.y += t.y; s.z += t.z; s.w += t.w;
    }
    reinterpret_cast<float4*>(out)[i] = s;
}

// ---------------------------------------------------------------- launch
extern "C" void kernel_launch(void* const* d_in, const int* in_sizes, int n_in,
                              void* d_out, int out_size)
{
    const float* inputs = nullptr;
    const float* adj = nullptr;
    const float* weights = nullptr;
    for (int i = 0; i < n_in; ++i) {
        long sz = (long)in_sizes[i];
        if (sz == (long)M_TOTAL * D_IN)         inputs  = (const float*)d_in[i];
        else if (sz == (long)M_TOTAL * M_TOTAL) adj     = (const float*)d_in[i];
        else if (sz == (long)D_IN * D_OUT)      weights = (const float*)d_in[i];
    }

    __half *xT = nullptr, *WT = nullptr;
    float  *part = nullptr;
    cudaGetSymbolAddress((void**)&xT, g_xT);
    cudaGetSymbolAddress((void**)&WT, g_WT);
    cudaGetSymbolAddress((void**)&part, g_part);
    cudaFuncSetAttribute((const void*)gemm_f16<true,  false>,
                         cudaFuncAttributeMaxDynamicSharedMemorySize, SMEM_BYTES);
    cudaFuncSetAttribute((const void*)gemm_f16<false, true>,
                         cudaFuncAttributeMaxDynamicSharedMemorySize, SMEM_BYTES);

    // 1) WT = fp16(W^T); reset ticket
    transposeW_kernel<<<(D_IN * D_OUT) / 256, 256>>>(weights, WT);
    // 2) xT = fp16((inputs @ W)^T)
    gemm_f16<true,  false><<<M_TOTAL / 128, 256, SMEM_BYTES>>>(
        inputs, WT, (float*)xT, D_IN, D_IN / KCHUNK);
    // 3) partials = adj @ x  (persistent, split-K=8)
    gemm_f16<false, true><<<296, 256, SMEM_BYTES>>>(
        adj, xT, part, M_TOTAL, CH_UNIT);
    // 4) out = sum partials
    reduce_kernel<<<(M_TOTAL * D_OUT / 4) / 256, 256>>>((float*)d_out);
}